// round 1
// baseline (speedup 1.0000x reference)
#include <cuda_runtime.h>

#define S    512
#define NA   180
#define NB   4
#define WSIZE 52
#define PI_F 3.14159265358979323846

// scratch: filtered sinogram, layout [b][a][s] (angle rows contiguous)
__device__ float g_xf[NB * NA * S];

// ---------------------------------------------------------------------------
// Stage 1: ramp filter along detector axis.
// One block per (b, a). 128 threads, 4 outputs each (s, s+128, s+256, s+384).
// xfilt[s] = 0.5*x[s] + sum_{j=0..255} g[2j+1]*(x[s-d]+x[s+d]),  d=2j+1,
// with zero padding outside [0, 512).
// ---------------------------------------------------------------------------
__global__ void __launch_bounds__(128) filter_kernel(const float* __restrict__ x) {
    const int a = blockIdx.x % NA;
    const int b = blockIdx.x / NA;

    __shared__ float sxp[3 * S];   // [0,512) zeros | [512,1024) data | [1024,1536) zeros
    __shared__ float sg[256];      // g[2j+1] = -2/(pi*(2j+1))^2

    const int t = threadIdx.x;     // 0..127

    #pragma unroll
    for (int i = t; i < S; i += 128) {
        sxp[i]         = 0.0f;
        sxp[2 * S + i] = 0.0f;
        sxp[S + i]     = x[(b * S + i) * NA + a];
    }
    #pragma unroll
    for (int i = t; i < 256; i += 128) {
        float d = (float)(2 * i + 1);
        sg[i] = -2.0f / ((float)(PI_F * PI_F) * d * d);
    }
    __syncthreads();

    const float* xc = &sxp[S + t];
    float acc0 = 0.5f * xc[0];
    float acc1 = 0.5f * xc[128];
    float acc2 = 0.5f * xc[256];
    float acc3 = 0.5f * xc[384];

    #pragma unroll 4
    for (int j = 0; j < 256; ++j) {
        const int d = 2 * j + 1;
        const float g = sg[j];
        acc0 = fmaf(g, xc[0   - d] + xc[0   + d], acc0);
        acc1 = fmaf(g, xc[128 - d] + xc[128 + d], acc1);
        acc2 = fmaf(g, xc[256 - d] + xc[256 + d], acc2);
        acc3 = fmaf(g, xc[384 - d] + xc[384 + d], acc3);
    }

    float* o = &g_xf[(b * NA + a) * S];
    o[t]       = acc0;
    o[t + 128] = acc1;
    o[t + 256] = acc2;
    o[t + 384] = acc3;
}

// ---------------------------------------------------------------------------
// Stage 2: backprojection.
// Grid (16,16,B): each block does a 32x32 pixel tile for one batch.
// 256 threads, 4 pixels each (x = tid&31, y = wy + {0,8,16,24}).
// All 180 per-angle detector windows (WSIZE floats each, zero-padded) are
// staged in shared memory up front; hot loop is pure smem.
// ---------------------------------------------------------------------------
__global__ void __launch_bounds__(256) backproj_kernel(float* __restrict__ out) {
    __shared__ float win[NA * WSIZE];
    __shared__ float s_c[NA], s_s[NA], s_fb[NA];
    __shared__ int   s_w0[NA];

    const int tid = threadIdx.x;
    const int b   = blockIdx.z;
    const int x0  = blockIdx.x * 32;
    const int y0  = blockIdx.y * 32;
    const int lx  = tid & 31;
    const int wy  = tid >> 5;

    const float invh = 2.0f / 511.0f;

    // ---- early out: tile fully outside the unit circle ----
    {
        float ux0 = fmaf((float)x0,        invh, -1.0f);
        float ux1 = fmaf((float)(x0 + 31), invh, -1.0f);
        float uy0 = fmaf((float)y0,        invh, -1.0f);
        float uy1 = fmaf((float)(y0 + 31), invh, -1.0f);
        float mx = (ux0 <= 0.0f && ux1 >= 0.0f) ? 0.0f : fminf(fabsf(ux0), fabsf(ux1));
        float my = (uy0 <= 0.0f && uy1 >= 0.0f) ? 0.0f : fminf(fabsf(uy0), fabsf(uy1));
        if (mx * mx + my * my > 1.0f) {
            #pragma unroll
            for (int j = 0; j < 4; ++j) {
                int y = y0 + wy + 8 * j;
                out[(b * S + y) * S + x0 + lx] = 0.0f;
            }
            return;
        }
    }

    // ---- per-angle tables ----
    if (tid < NA) {
        float th = (float)tid * (float)(PI_F / 180.0);
        float sn, cs;
        sincosf(th, &sn, &cs);
        // p = 255.5 + (x-255.5)*cos - (y-255.5)*sin
        float pb = 255.5f + ((float)x0 - 255.5f) * cs - ((float)y0 - 255.5f) * sn;
        float ex = cs * 31.0f;
        float ey = -sn * 31.0f;
        float pmin = pb + fminf(ex, 0.0f) + fminf(ey, 0.0f);
        int w0 = (int)floorf(pmin) - 2;   // 2 slack below; window width <= 44+3 << WSIZE
        s_w0[tid] = w0;
        s_c[tid]  = cs;
        s_s[tid]  = sn;
        s_fb[tid] = pb - (float)w0;       // local p base, guaranteed in [2, 49)
    }
    __syncthreads();

    // ---- cooperative window load (zero padding == reference validity mask) ----
    for (int i = tid; i < NA * WSIZE; i += 256) {
        int a  = i / WSIZE;
        int o  = i - a * WSIZE;
        int gi = s_w0[a] + o;
        float v = 0.0f;
        if ((unsigned)gi < (unsigned)S) v = g_xf[(b * NA + a) * S + gi];
        win[i] = v;
    }
    __syncthreads();

    // ---- main accumulation ----
    const float fx  = (float)lx;
    const float fy0 = (float)wy;
    const float fy1 = fy0 + 8.0f;
    const float fy2 = fy0 + 16.0f;
    const float fy3 = fy0 + 24.0f;

    float acc0 = 0.0f, acc1 = 0.0f, acc2 = 0.0f, acc3 = 0.0f;

    for (int a = 0; a < NA; ++a) {
        const float cs = s_c[a];
        const float ns = -s_s[a];
        const float bx = fmaf(cs, fx, s_fb[a]);
        const float* w = &win[a * WSIZE];

        {
            float p  = fmaf(ns, fy0, bx);
            float fp = floorf(p);
            int   i0 = (int)fp;
            float wf = p - fp;
            float lo = w[i0], hi = w[i0 + 1];
            acc0 = fmaf(wf, hi - lo, acc0 + lo);
        }
        {
            float p  = fmaf(ns, fy1, bx);
            float fp = floorf(p);
            int   i0 = (int)fp;
            float wf = p - fp;
            float lo = w[i0], hi = w[i0 + 1];
            acc1 = fmaf(wf, hi - lo, acc1 + lo);
        }
        {
            float p  = fmaf(ns, fy2, bx);
            float fp = floorf(p);
            int   i0 = (int)fp;
            float wf = p - fp;
            float lo = w[i0], hi = w[i0 + 1];
            acc2 = fmaf(wf, hi - lo, acc2 + lo);
        }
        {
            float p  = fmaf(ns, fy3, bx);
            float fp = floorf(p);
            int   i0 = (int)fp;
            float wf = p - fp;
            float lo = w[i0], hi = w[i0 + 1];
            acc3 = fmaf(wf, hi - lo, acc3 + lo);
        }
    }

    // ---- circle mask + scale + store ----
    const float scale = (float)(PI_F / (2.0 * NA));
    const float ux = fmaf((float)(x0 + lx), invh, -1.0f);
    const float uxx = ux * ux;

    {
        int y = y0 + wy;
        float uy = fmaf((float)y, invh, -1.0f);
        out[(b * S + y) * S + x0 + lx] = (uxx + uy * uy <= 1.0f) ? acc0 * scale : 0.0f;
    }
    {
        int y = y0 + wy + 8;
        float uy = fmaf((float)y, invh, -1.0f);
        out[(b * S + y) * S + x0 + lx] = (uxx + uy * uy <= 1.0f) ? acc1 * scale : 0.0f;
    }
    {
        int y = y0 + wy + 16;
        float uy = fmaf((float)y, invh, -1.0f);
        out[(b * S + y) * S + x0 + lx] = (uxx + uy * uy <= 1.0f) ? acc2 * scale : 0.0f;
    }
    {
        int y = y0 + wy + 24;
        float uy = fmaf((float)y, invh, -1.0f);
        out[(b * S + y) * S + x0 + lx] = (uxx + uy * uy <= 1.0f) ? acc3 * scale : 0.0f;
    }
}

// ---------------------------------------------------------------------------
extern "C" void kernel_launch(void* const* d_in, const int* in_sizes, int n_in,
                              void* d_out, int out_size) {
    const float* x = (const float*)d_in[0];
    float* out = (float*)d_out;

    filter_kernel<<<NB * NA, 128>>>(x);

    dim3 grid(16, 16, NB);
    backproj_kernel<<<grid, 256>>>(out);
}

// round 2
// speedup vs baseline: 1.1743x; 1.1743x over previous
#include <cuda_runtime.h>

#define S    512
#define NA   180
#define NB   4
#define WS   48          // window entries per angle (float2)
#define HALF_A 90        // angles per phase
#define PI_D 3.14159265358979323846
#define MAGICF 8388608.0f      // 2^23

// filtered sinogram + per-bin forward difference, layout [b][a][s]
__device__ float2 g_xf2[NB * NA * S];

// ---------------------------------------------------------------------------
// Stage 1: ramp filter along detector axis. One block per (b, a), 128 threads.
// xfilt[s] = 0.5*x[s] + sum_{d odd} (-2/(pi d)^2) * (x[s-d] + x[s+d])
// Emits float2 (w[s], w[s+1]-w[s]) with w[512] == 0.
// ---------------------------------------------------------------------------
__global__ void __launch_bounds__(128) filter_kernel(const float* __restrict__ x) {
    const int a = blockIdx.x % NA;
    const int b = blockIdx.x / NA;

    __shared__ float sxp[3 * S];
    __shared__ float sg[256];
    __shared__ float sout[S + 1];

    const int t = threadIdx.x;

    #pragma unroll
    for (int i = t; i < S; i += 128) {
        sxp[i]         = 0.0f;
        sxp[2 * S + i] = 0.0f;
        sxp[S + i]     = x[(b * S + i) * NA + a];
    }
    #pragma unroll
    for (int i = t; i < 256; i += 128) {
        float d = (float)(2 * i + 1);
        sg[i] = -2.0f / ((float)(PI_D * PI_D) * d * d);
    }
    __syncthreads();

    const float* xc = &sxp[S + t];
    float acc0 = 0.5f * xc[0];
    float acc1 = 0.5f * xc[128];
    float acc2 = 0.5f * xc[256];
    float acc3 = 0.5f * xc[384];

    #pragma unroll 4
    for (int j = 0; j < 256; ++j) {
        const int d = 2 * j + 1;
        const float g = sg[j];
        acc0 = fmaf(g, xc[0   - d] + xc[0   + d], acc0);
        acc1 = fmaf(g, xc[128 - d] + xc[128 + d], acc1);
        acc2 = fmaf(g, xc[256 - d] + xc[256 + d], acc2);
        acc3 = fmaf(g, xc[384 - d] + xc[384 + d], acc3);
    }

    sout[t]       = acc0;
    sout[t + 128] = acc1;
    sout[t + 256] = acc2;
    sout[t + 384] = acc3;
    if (t == 0) sout[S] = 0.0f;
    __syncthreads();

    float2* o = &g_xf2[(b * NA + a) * S];
    #pragma unroll
    for (int i = t; i < S; i += 128) {
        float lo = sout[i];
        o[i] = make_float2(lo, sout[i + 1] - lo);
    }
}

// ---------------------------------------------------------------------------
// Stage 2: backprojection. Grid (16,16,B), 256 threads, 32x32 tile, 4 px/thread.
// Two phases of 90 angles; each phase stages 90 zero-padded detector windows
// as float2 (lo, d) in static smem (~38KB total) for 5-6 blocks/SM.
// ---------------------------------------------------------------------------
__global__ void __launch_bounds__(256, 5) backproj_kernel(float* __restrict__ out) {
    __shared__ float2 win2[HALF_A * WS];     // 34560 B
    __shared__ float4 cons[NA];              //  2880 B
    __shared__ int    w0s[NA];               //   720 B

    const int tid = threadIdx.x;
    const int b   = blockIdx.z;
    const int x0  = blockIdx.x * 32;
    const int y0  = blockIdx.y * 32;
    const int lx  = tid & 31;
    const int wy  = tid >> 5;

    const float invh = 2.0f / 511.0f;

    // ---- early out: tile fully outside the unit circle ----
    {
        float ux0 = fmaf((float)x0,        invh, -1.0f);
        float ux1 = fmaf((float)(x0 + 31), invh, -1.0f);
        float uy0 = fmaf((float)y0,        invh, -1.0f);
        float uy1 = fmaf((float)(y0 + 31), invh, -1.0f);
        float mx = (ux0 <= 0.0f && ux1 >= 0.0f) ? 0.0f : fminf(fabsf(ux0), fabsf(ux1));
        float my = (uy0 <= 0.0f && uy1 >= 0.0f) ? 0.0f : fminf(fabsf(uy0), fabsf(uy1));
        if (mx * mx + my * my > 1.0f) {
            #pragma unroll
            for (int j = 0; j < 4; ++j) {
                int y = y0 + wy + 8 * j;
                out[(b * S + y) * S + x0 + lx] = 0.0f;
            }
            return;
        }
    }

    // ---- per-angle tables ----
    if (tid < NA) {
        float th = (float)tid * (float)(PI_D / 180.0);
        float sn, cs;
        sincosf(th, &sn, &cs);
        float pb = 255.5f + ((float)x0 - 255.5f) * cs - ((float)y0 - 255.5f) * sn;
        float pmin = pb + fminf(cs * 31.0f, 0.0f) + fminf(-sn * 31.0f, 0.0f);
        int w0 = (int)floorf(pmin) - 1;      // local p in [1, 45.9) -> idx <= 46 < WS
        w0s[tid] = w0;
        int aw = (tid < HALF_A) ? tid : (tid - HALF_A);
        unsigned wbase = (unsigned)__cvta_generic_to_shared(&win2[aw * WS])
                         - 0x58000000u;      // -(0x4B000000 * 8) mod 2^32
        cons[tid] = make_float4(cs, -sn, pb - (float)w0, __uint_as_float(wbase));
    }
    __syncthreads();

    const float fx  = (float)lx;
    const float fy0 = (float)wy;
    const float fy1 = fy0 + 8.0f;
    const float fy2 = fy0 + 16.0f;
    const float fy3 = fy0 + 24.0f;

    float aL0 = 0.f, aF0 = 0.f, aL1 = 0.f, aF1 = 0.f;
    float aL2 = 0.f, aF2 = 0.f, aL3 = 0.f, aF3 = 0.f;

    const float2* __restrict__ grow = &g_xf2[b * NA * S];

    const int al = tid / WS;               // 0..4 for tid<240
    const int oo = tid - al * WS;

    #pragma unroll 1
    for (int phase = 0; phase < 2; ++phase) {
        const int abase = phase * HALF_A;

        // ---- cooperative window load (240 active threads) ----
        if (tid < 240) {
            #pragma unroll
            for (int ar = al; ar < HALF_A; ar += 5) {
                int a  = abase + ar;
                int gi = w0s[a] + oo;
                float2 v;
                if ((unsigned)gi < (unsigned)S) {
                    v = grow[a * S + gi];              // d at 511 already -w[511]
                } else if (gi == -1) {
                    v = make_float2(0.0f, grow[a * S].x);
                } else {
                    v = make_float2(0.0f, 0.0f);
                }
                win2[ar * WS + oo] = v;
            }
        }
        __syncthreads();

        // ---- accumulate 90 angles ----
        #pragma unroll 2
        for (int a = abase; a < abase + HALF_A; ++a) {
            float4 c = cons[a];
            float bx = fmaf(c.x, fx, c.z);
            unsigned wb = __float_as_uint(c.w);

#define SAMPLE(FY, AL, AF)                                                    \
            {                                                                 \
                float p  = fmaf(c.y, (FY), bx);                               \
                float pm = __fadd_rd(p, MAGICF);                              \
                unsigned sa = wb + __float_as_uint(pm) * 8u;                  \
                float fl = pm - MAGICF;                                       \
                float fr = p - fl;                                            \
                float lo, dd;                                                 \
                asm("ld.shared.v2.f32 {%0, %1}, [%2];"                        \
                    : "=f"(lo), "=f"(dd) : "r"(sa));                          \
                AL += lo;                                                     \
                AF = fmaf(fr, dd, AF);                                        \
            }

            SAMPLE(fy0, aL0, aF0)
            SAMPLE(fy1, aL1, aF1)
            SAMPLE(fy2, aL2, aF2)
            SAMPLE(fy3, aL3, aF3)
#undef SAMPLE
        }
        __syncthreads();
    }

    // ---- circle mask + scale + store ----
    const float scale = (float)(PI_D / (2.0 * NA));
    const float ux  = fmaf((float)(x0 + lx), invh, -1.0f);
    const float uxx = ux * ux;

    {
        int y = y0 + wy;
        float uy = fmaf((float)y, invh, -1.0f);
        out[(b * S + y) * S + x0 + lx] = (uxx + uy * uy <= 1.0f) ? (aL0 + aF0) * scale : 0.0f;
    }
    {
        int y = y0 + wy + 8;
        float uy = fmaf((float)y, invh, -1.0f);
        out[(b * S + y) * S + x0 + lx] = (uxx + uy * uy <= 1.0f) ? (aL1 + aF1) * scale : 0.0f;
    }
    {
        int y = y0 + wy + 16;
        float uy = fmaf((float)y, invh, -1.0f);
        out[(b * S + y) * S + x0 + lx] = (uxx + uy * uy <= 1.0f) ? (aL2 + aF2) * scale : 0.0f;
    }
    {
        int y = y0 + wy + 24;
        float uy = fmaf((float)y, invh, -1.0f);
        out[(b * S + y) * S + x0 + lx] = (uxx + uy * uy <= 1.0f) ? (aL3 + aF3) * scale : 0.0f;
    }
}

// ---------------------------------------------------------------------------
extern "C" void kernel_launch(void* const* d_in, const int* in_sizes, int n_in,
                              void* d_out, int out_size) {
    const float* x = (const float*)d_in[0];
    float* out = (float*)d_out;

    filter_kernel<<<NB * NA, 128>>>(x);

    dim3 grid(16, 16, NB);
    backproj_kernel<<<grid, 256>>>(out);
}

// round 3
// speedup vs baseline: 1.4275x; 1.2156x over previous
#include <cuda_runtime.h>

#define S    512
#define NA   180
#define NB   4
#define WS   48
#define HALF_A 90
#define PI_D 3.14159265358979323846

// filtered sinogram windows: (e, d) with e = w[s] + 0.5*d, d = w[s+1]-w[s]; layout [b][a][s]
__device__ float2 g_xf2[NB * NA * S];

// ---------------------------------------------------------------------------
// Stage 1: ramp filter, register-sliding FIR.
// One block per (b,a), 64 threads, 8 consecutive outputs per thread.
// Skewed smem: phys(i) = i + (i>>3); lane addresses (stride 8 in i) become
// stride 9 -> conflict-free. For i = 8t + C: phys = 9t + C + (C>>3) exactly.
// ---------------------------------------------------------------------------
#define OFFM(d) ((d) + ((1 + (d)) >> 3))
#define OFFP(d) ((d) + ((7 + (d)) >> 3))

__global__ void __launch_bounds__(64) filter_kernel(const float* __restrict__ x) {
    const int a = blockIdx.x % NA;
    const int b = blockIdx.x / NA;

    __shared__ float P[1736];      // skewed padded signal, logical i in [0,1536)
    __shared__ float sg[256];
    __shared__ float sw[S + 8];

    const int t = threadIdx.x;     // 0..63

    // zero pad regions (logical [0,512) and [1024,1536)); data region written below
    #pragma unroll
    for (int i = t; i < 512; i += 64) {
        P[i + (i >> 3)] = 0.0f;
        int j = i + 1024;
        P[j + (j >> 3)] = 0.0f;
    }
    #pragma unroll
    for (int i = t; i < S; i += 64) {
        int ii = i + 512;
        P[ii + (ii >> 3)] = x[(b * S + i) * NA + a];
    }
    #pragma unroll
    for (int i = t; i < 256; i += 64) {
        float dd = (float)(2 * i + 1);
        sg[i] = -2.0f / ((float)(PI_D * PI_D) * dd * dd);
    }
    __syncthreads();

    // accumulators: center tap 0.5*x[s], s = 8t+k ; phys(8t+512+k) = 9t+576+k
    float acc[8];
    #pragma unroll
    for (int k = 0; k < 8; ++k)
        acc[k] = 0.5f * P[9 * t + 576 + k];

    // minus side: i = 8t + 1 + 16g + 2jj + k        (d = 511-16g-2jj)
    // plus  side: i = 8t + 1007 + 16 - 16g - 2jj + k  -> delta' = 16-2jj+k vs CgL=1007-16g
    float Am[16], Ap[16];
    int A0 = 9 * t + 1;                 // 9t + Cg + (Cg>>3), Cg=1 (Cg&7==1)
    int A1 = 9 * t + 1132;              // 9t + 1007 + 125    (CgL&7==7)

    #pragma unroll
    for (int d0 = 0; d0 < 8; ++d0) {
        Am[d0] = P[A0 + OFFM(d0)];           // logical delta 0..7
        Ap[d0] = P[A1 + OFFP(16 + d0)];      // eps 0..7 -> delta' 16..23
    }

    #pragma unroll 1
    for (int g = 0; g < 32; ++g) {
        #pragma unroll
        for (int jj = 0; jj < 8; ++jj) {
            float gc = sg[255 - 8 * g - jj];
            #pragma unroll
            for (int k = 0; k < 8; ++k) {
                float av = Am[(2 * jj + k) & 15];
                float bv = Ap[(k - 2 * jj) & 15];
                acc[k] = fmaf(gc, av + bv, acc[k]);
            }
            // fetch next-tap entries
            Am[(2 * jj + 8) & 15] = P[A0 + OFFM(2 * jj + 8)];
            Am[(2 * jj + 9) & 15] = P[A0 + OFFM(2 * jj + 9)];
            Ap[(14 - 2 * jj) & 15] = P[A1 + OFFP(14 - 2 * jj)];
            Ap[(15 - 2 * jj) & 15] = P[A1 + OFFP(15 - 2 * jj)];
        }
        A0 += 18;
        A1 -= 18;
    }

    #pragma unroll
    for (int k = 0; k < 8; ++k)
        sw[8 * t + k] = acc[k];
    if (t == 0) sw[S] = 0.0f;
    __syncthreads();

    float2* o = &g_xf2[(b * NA + a) * S];
    #pragma unroll
    for (int k = 0; k < 8; ++k) {
        int s = 8 * t + k;
        float lo = sw[s];
        float d  = sw[s + 1] - lo;
        o[s] = make_float2(fmaf(0.5f, d, lo), d);
    }
}

// ---------------------------------------------------------------------------
// Stage 2: backprojection. Grid (16,16,B), 256 threads, 32x32 tile, 4 px/thread.
// Packed f32x2 front-end (p, magic-RN floor, frac). Sample = e[F] + fr*d[F],
// exact for either tie direction since e = w + 0.5*d and p' = p - 0.5.
// ---------------------------------------------------------------------------
__global__ void __launch_bounds__(256, 4) backproj_kernel(float* __restrict__ out) {
    __shared__ float2 win2[HALF_A * WS];     // 34560 B
    __shared__ float4 cons[NA];              //  2880 B
    __shared__ int    w0s[NA];               //   720 B

    const int tid = threadIdx.x;
    const int b   = blockIdx.z;
    const int x0  = blockIdx.x * 32;
    const int y0  = blockIdx.y * 32;
    const int lx  = tid & 31;
    const int wy  = tid >> 5;

    const float invh = 2.0f / 511.0f;

    // ---- early out: tile fully outside the unit circle ----
    {
        float ux0 = fmaf((float)x0,        invh, -1.0f);
        float ux1 = fmaf((float)(x0 + 31), invh, -1.0f);
        float uy0 = fmaf((float)y0,        invh, -1.0f);
        float uy1 = fmaf((float)(y0 + 31), invh, -1.0f);
        float mx = (ux0 <= 0.0f && ux1 >= 0.0f) ? 0.0f : fminf(fabsf(ux0), fabsf(ux1));
        float my = (uy0 <= 0.0f && uy1 >= 0.0f) ? 0.0f : fminf(fabsf(uy0), fabsf(uy1));
        if (mx * mx + my * my > 1.0f) {
            #pragma unroll
            for (int j = 0; j < 4; ++j) {
                int y = y0 + wy + 8 * j;
                out[(b * S + y) * S + x0 + lx] = 0.0f;
            }
            return;
        }
    }

    // ---- per-angle tables ----
    if (tid < NA) {
        float th = (float)tid * (float)(PI_D / 180.0);
        float sn, cs;
        sincosf(th, &sn, &cs);
        float pb = 255.5f + ((float)x0 - 255.5f) * cs - ((float)y0 - 255.5f) * sn;
        float pmin = pb + fminf(cs * 31.0f, 0.0f) + fminf(-sn * 31.0f, 0.0f);
        int w0 = (int)floorf(pmin) - 1;      // local p in [1, ~46)
        w0s[tid] = w0;
        cons[tid] = make_float4(cs, pb - (float)w0 - 0.5f, -sn, -sn);
    }
    __syncthreads();

    const float fx = (float)lx;
    unsigned long long FY01, FY23;
    {
        float fy0 = (float)wy, fy1 = fy0 + 8.0f, fy2 = fy0 + 16.0f, fy3 = fy0 + 24.0f;
        asm("mov.b64 %0, {%1, %2};" : "=l"(FY01) : "f"(fy0), "f"(fy1));
        asm("mov.b64 %0, {%1, %2};" : "=l"(FY23) : "f"(fy2), "f"(fy3));
    }
    const unsigned long long MAG2  = 0x4B0000004B000000ull;  // {2^23, 2^23}
    const unsigned long long NMAG2 = 0xCB000000CB000000ull;  // {-2^23, -2^23}
    const unsigned long long NONE2 = 0xBF800000BF800000ull;  // {-1, -1}

    const unsigned wbase0 = (unsigned)__cvta_generic_to_shared(win2) - 0x58000000u;

    float aL0 = 0.f, aF0 = 0.f, aL1 = 0.f, aF1 = 0.f;
    float aL2 = 0.f, aF2 = 0.f, aL3 = 0.f, aF3 = 0.f;

    const float2* __restrict__ grow = &g_xf2[b * NA * S];

    const int al = tid / WS;               // 0..4 for tid<240
    const int oo = tid - al * WS;

    #pragma unroll 1
    for (int phase = 0; phase < 2; ++phase) {
        const int abase = phase * HALF_A;

        // ---- cooperative window load (240 active threads) ----
        if (tid < 240) {
            #pragma unroll
            for (int ar = al; ar < HALF_A; ar += 5) {
                int a  = abase + ar;
                int gi = w0s[a] + oo;
                float2 v;
                if ((unsigned)gi < (unsigned)S) {
                    v = grow[a * S + gi];
                } else if (gi == -1) {
                    float2 v0 = grow[a * S];
                    float w0v = v0.x - 0.5f * v0.y;     // w[0] = e0 - 0.5*d0
                    v = make_float2(0.5f * w0v, w0v);
                } else {
                    v = make_float2(0.0f, 0.0f);
                }
                win2[ar * WS + oo] = v;
            }
        }
        __syncthreads();

        // ---- accumulate 90 angles ----
        unsigned wb = wbase0;
        #pragma unroll 2
        for (int a = abase; a < abase + HALF_A; ++a, wb += WS * 8u) {
            float4 c = cons[a];                      // {cs, cz, ns, ns}
            float bx = fmaf(c.x, fx, c.y);

            unsigned m0, m1, m2, m3;
            unsigned long long FR01, FR23;
            asm("{\n\t"
                ".reg .b64 ns2, bx2, p01, p23, pm01, pm23, fl01, fl23, q01, q23;\n\t"
                "mov.b64 ns2, {%6, %6};\n\t"
                "mov.b64 bx2, {%7, %7};\n\t"
                "fma.rn.f32x2 p01, ns2, %8, bx2;\n\t"
                "fma.rn.f32x2 p23, ns2, %9, bx2;\n\t"
                "add.rn.f32x2 pm01, p01, %10;\n\t"
                "add.rn.f32x2 pm23, p23, %10;\n\t"
                "add.rn.f32x2 fl01, pm01, %11;\n\t"
                "add.rn.f32x2 fl23, pm23, %11;\n\t"
                "fma.rn.f32x2 q01, fl01, %12, p01;\n\t"
                "fma.rn.f32x2 q23, fl23, %12, p23;\n\t"
                "mov.b64 {%0, %1}, pm01;\n\t"
                "mov.b64 {%2, %3}, pm23;\n\t"
                "mov.b64 %4, q01;\n\t"
                "mov.b64 %5, q23;\n\t"
                "}"
                : "=r"(m0), "=r"(m1), "=r"(m2), "=r"(m3), "=l"(FR01), "=l"(FR23)
                : "f"(c.z), "f"(bx), "l"(FY01), "l"(FY23),
                  "l"(MAG2), "l"(NMAG2), "l"(NONE2));

            float fr0 = __uint_as_float((unsigned)FR01);
            float fr1 = __uint_as_float((unsigned)(FR01 >> 32));
            float fr2 = __uint_as_float((unsigned)FR23);
            float fr3 = __uint_as_float((unsigned)(FR23 >> 32));

#define SAMPLE(M, FR, AL, AF)                                                 \
            {                                                                 \
                unsigned sa = wb + (M) * 8u;                                  \
                float e, d;                                                   \
                asm("ld.shared.v2.f32 {%0, %1}, [%2];"                        \
                    : "=f"(e), "=f"(d) : "r"(sa));                            \
                AL += e;                                                      \
                AF = fmaf((FR), d, AF);                                       \
            }
            SAMPLE(m0, fr0, aL0, aF0)
            SAMPLE(m1, fr1, aL1, aF1)
            SAMPLE(m2, fr2, aL2, aF2)
            SAMPLE(m3, fr3, aL3, aF3)
#undef SAMPLE
        }
        __syncthreads();
    }

    // ---- circle mask + scale + store ----
    const float scale = (float)(PI_D / (2.0 * NA));
    const float ux  = fmaf((float)(x0 + lx), invh, -1.0f);
    const float uxx = ux * ux;

    {
        int y = y0 + wy;
        float uy = fmaf((float)y, invh, -1.0f);
        out[(b * S + y) * S + x0 + lx] = (uxx + uy * uy <= 1.0f) ? (aL0 + aF0) * scale : 0.0f;
    }
    {
        int y = y0 + wy + 8;
        float uy = fmaf((float)y, invh, -1.0f);
        out[(b * S + y) * S + x0 + lx] = (uxx + uy * uy <= 1.0f) ? (aL1 + aF1) * scale : 0.0f;
    }
    {
        int y = y0 + wy + 16;
        float uy = fmaf((float)y, invh, -1.0f);
        out[(b * S + y) * S + x0 + lx] = (uxx + uy * uy <= 1.0f) ? (aL2 + aF2) * scale : 0.0f;
    }
    {
        int y = y0 + wy + 24;
        float uy = fmaf((float)y, invh, -1.0f);
        out[(b * S + y) * S + x0 + lx] = (uxx + uy * uy <= 1.0f) ? (aL3 + aF3) * scale : 0.0f;
    }
}

// ---------------------------------------------------------------------------
extern "C" void kernel_launch(void* const* d_in, const int* in_sizes, int n_in,
                              void* d_out, int out_size) {
    const float* x = (const float*)d_in[0];
    float* out = (float*)d_out;

    filter_kernel<<<NB * NA, 64>>>(x);

    dim3 grid(16, 16, NB);
    backproj_kernel<<<grid, 256>>>(out);
}